// round 12
// baseline (speedup 1.0000x reference)
#include <cuda_runtime.h>
#include <cstdint>

#define BH   32
#define LSEQ 4096
#define DK   16
#define DV   64
#define CS   256
#define NC   16

// Symmetric-pair state: 136 pair rows (d<=e) + 16 linear rows + 1 ones row,
// padded to 160 rows x 72 cols (64 v-cols + 1 aux-sum col + 7 zero pads).
#define NP   160
#define NW   72
#define ST_STRIDE (NP * NW)   // 11520

// paired-K layout stride for k_build A (32 k8-groups * 8 + 8 pad)
#define SKQ_STRIDE 264

__device__ float g_state[(size_t)BH * NC * ST_STRIDE];

__device__ __forceinline__ unsigned f2t(float x) {
    unsigned u;
    asm("cvt.rna.tf32.f32 %0, %1;" : "=r"(u) : "f"(x));
    return u;
}
__device__ __forceinline__ float f2tf(float x) { return __uint_as_float(f2t(x)); }
__device__ __forceinline__ unsigned fas(float x) { return __float_as_uint(x); }
__device__ __forceinline__ unsigned shflu(unsigned v, int src) {
    return __shfl_sync(0xffffffffu, v, src);
}

__device__ __forceinline__ void mma8(float* c, unsigned a0, unsigned a1,
                                     unsigned a2, unsigned a3,
                                     unsigned b0, unsigned b1) {
    asm volatile(
        "mma.sync.aligned.m16n8k8.row.col.f32.tf32.tf32.f32 "
        "{%0,%1,%2,%3},{%4,%5,%6,%7},{%8,%9},{%0,%1,%2,%3};"
        : "+f"(c[0]), "+f"(c[1]), "+f"(c[2]), "+f"(c[3])
        : "r"(a0), "r"(a1), "r"(a2), "r"(a3), "r"(b0), "r"(b1));
}

// p -> (d, e, w). d,e in [0,16]; index 16 hits the pad slot (=1.0f).
// spde packs (2d | 2e<<8) for the z-scalar loop.
__device__ __forceinline__ void lut_build(int* spd, int* spe, float* sw,
                                          int* spde, int tid) {
    if (tid < NP) {
        int p = tid, d = 0, e;
        float w;
        if (p < 136) {
            int base = 0;
            while (base + (16 - d) <= p) { base += 16 - d; d++; }
            e = d + (p - base);
            w = (d == e) ? 0.5f : 1.0f;
        } else if (p < 152) { d = p - 136; e = 16; w = 1.f; }
        else if (p == 152) { d = 16; e = 16; w = 1.f; }
        else               { d = 16; e = 16; w = 0.f; }
        spd[p] = d; spe[p] = e; sw[p] = w;
        spde[p] = (2 * d) | ((2 * e) << 8);
    }
}

// ---------------------------------------------------------------------------
// Kernel 1: state build = single GEMM  st[160x72] = A[160x256] @ B[256x72]
// Pair-packed layouts: A operands via LDS.64 (rows c,c+4), B via LDS.64
// (rows 8k+tg, 8k+tg+4).  480 threads, 2 CTAs/SM.
// ---------------------------------------------------------------------------
__global__ __launch_bounds__(480, 2)
void k_build(const float* __restrict__ kin, const float* __restrict__ vin) {
    const int head = blockIdx.x, ch = blockIdx.y;
    extern __shared__ float sm[];
    float* skq = sm;                      // [17][SKQ_STRIDE] paired k
    float* sBq = skq + 17 * SKQ_STRIDE;   // [32][72][8] paired V+aux
    int*   spd = (int*)(sBq + 32 * NW * 8);
    int*   spe = spd + NP;
    float* sw  = (float*)(spe + NP);
    int*   spde = (int*)(sw + NP);
    unsigned* sBu = (unsigned*)sBq;

    const float* kg = kin + ((size_t)head * LSEQ + (size_t)ch * CS) * DK;
    const float* vg = vin + ((size_t)head * LSEQ + (size_t)ch * CS) * DV;
    float* st = g_state + (size_t)(head * NC + ch) * ST_STRIDE;

    const int tid = threadIdx.x, warp = tid >> 5, lane = tid & 31;
    const int wm = warp / 3, wn = warp % 3, g = lane >> 2, tg = lane & 3;
    const int rb = 32 * wm, cb = 24 * wn;

    // stage k (paired over rows c, c+4): skq[idx][k8][tg][2]
    for (int i = tid; i < CS * DK; i += 480) {
        int c = i >> 4, idx = i & 15;
        int k8 = c >> 3, jj = c & 7;
        skq[idx * SKQ_STRIDE + k8 * 8 + (jj & 3) * 2 + (jj >> 2)] = f2tf(kg[i]);
    }
    for (int i = tid; i < CS; i += 480) {
        int k8 = i >> 3, jj = i & 7;
        skq[16 * SKQ_STRIDE + k8 * 8 + (jj & 3) * 2 + (jj >> 2)] = 1.0f;
    }
    // stage V + aux col (paired over rows 8k8+tg, 8k8+tg+4)
    for (int i = tid; i < CS * 18; i += 480) {
        int cc = i / 18, f4 = (i - cc * 18) * 4;
        int k8 = cc >> 3, jj = cc & 7, base = (jj & 3) * 2 + (jj >> 2);
        #pragma unroll
        for (int u = 0; u < 4; u++) {
            int f = f4 + u;
            float val = (f < 64) ? f2tf(vg[cc * 64 + f])
                                 : (f == 64 ? 1.0f : 0.f);
            sBq[(k8 * NW + f) * 8 + base] = val;
        }
    }
    lut_build(spd, spe, sw, spde, tid);
    __syncthreads();

    int rd[2][2], re[2][2];
    #pragma unroll
    for (int mt = 0; mt < 2; mt++) {
        int r0 = rb + 16 * mt + g;
        rd[mt][0] = spd[r0];     re[mt][0] = spe[r0];
        rd[mt][1] = spd[r0 + 8]; re[mt][1] = spe[r0 + 8];
    }

    float c[2][3][4];
    #pragma unroll
    for (int mt = 0; mt < 2; mt++)
        #pragma unroll
        for (int nt = 0; nt < 3; nt++)
            #pragma unroll
            for (int u = 0; u < 4; u++) c[mt][nt][u] = 0.f;

    #pragma unroll 4
    for (int ks = 0; ks < 32; ks++) {
        unsigned a[2][4];
        #pragma unroll
        for (int mt = 0; mt < 2; mt++) {
            float2 pd0 = *(float2*)&skq[rd[mt][0] * SKQ_STRIDE + ks * 8 + tg * 2];
            float2 pe0 = *(float2*)&skq[re[mt][0] * SKQ_STRIDE + ks * 8 + tg * 2];
            float2 pd1 = *(float2*)&skq[rd[mt][1] * SKQ_STRIDE + ks * 8 + tg * 2];
            float2 pe1 = *(float2*)&skq[re[mt][1] * SKQ_STRIDE + ks * 8 + tg * 2];
            a[mt][0] = fas(pd0.x * pe0.x);   // row r0,   col c
            a[mt][1] = fas(pd1.x * pe1.x);   // row r0+8, col c
            a[mt][2] = fas(pd0.y * pe0.y);   // row r0,   col c+4
            a[mt][3] = fas(pd1.y * pe1.y);   // row r0+8, col c+4
        }
        unsigned b[3][2];
        #pragma unroll
        for (int nt = 0; nt < 3; nt++) {
            uint2 bb = *(uint2*)&sBu[(ks * NW + cb + 8 * nt + g) * 8 + tg * 2];
            b[nt][0] = bb.x; b[nt][1] = bb.y;
        }
        #pragma unroll
        for (int mt = 0; mt < 2; mt++)
            #pragma unroll
            for (int nt = 0; nt < 3; nt++)
                mma8(c[mt][nt], a[mt][0], a[mt][1], a[mt][2], a[mt][3],
                     b[nt][0], b[nt][1]);
    }

    #pragma unroll
    for (int mt = 0; mt < 2; mt++)
        #pragma unroll
        for (int nt = 0; nt < 3; nt++) {
            int r0 = rb + 16 * mt + g, col = cb + 8 * nt + 2 * tg;
            *(float2*)&st[r0 * NW + col] =
                make_float2(c[mt][nt][0], c[mt][nt][1]);
            *(float2*)&st[(r0 + 8) * NW + col] =
                make_float2(c[mt][nt][2], c[mt][nt][3]);
        }
}

// ---------------------------------------------------------------------------
// Kernel 2: exclusive prefix scan over chunk axis. One element per thread.
// ---------------------------------------------------------------------------
__global__ void k_scan() {
    float* base = g_state + (size_t)blockIdx.x * NC * ST_STRIDE +
                  blockIdx.y * blockDim.x + threadIdx.x;
    float v[NC];
    #pragma unroll
    for (int c = 0; c < NC; c++) v[c] = base[(size_t)c * ST_STRIDE];
    float run = 0.f;
    #pragma unroll
    for (int c = 0; c < NC; c++) {
        float t = v[c];
        v[c] = run;
        run += t;
    }
    #pragma unroll
    for (int c = 0; c < NC; c++) base[(size_t)c * ST_STRIDE] = v[c];
}

// ---------------------------------------------------------------------------
// Kernel 3: output. 512 threads, 2 CTAs/SM. Mirrored row tiles. Pair-packed
// layouts: intra K via LDS.128, V/state via LDS.64, Q via LDS.64 (rows r,r+8).
// ---------------------------------------------------------------------------
__global__ __launch_bounds__(512, 2)
void k_main(const float* __restrict__ qin, const float* __restrict__ kin,
            const float* __restrict__ vin, float* __restrict__ out) {
    const int head = blockIdx.x, ch = blockIdx.y;
    extern __shared__ float sm[];
    float* sqp = sm;                      // [128][34]: rows (16t+g, 16t+g+8) paired
    float* sk4 = sqp + 128 * 34;          // [256][16]: idx order tg+4j
    float* sBq = sk4 + 256 * 16;          // [32][72][8]: V, later state (paired rows)
    float* szs = sBq + 32 * NW * 8;       // [256]
    int*   spd = (int*)(szs + 256);       // [160]
    int*   spe = spd + NP;
    float* sw  = (float*)(spe + NP);      // [160]
    int*   spde = (int*)(sw + NP);        // [160]
    float* swst = (float*)(spde + NP);    // [160] w*state[:,64]
    unsigned* sBu = (unsigned*)sBq;

    const float* qg = qin + ((size_t)head * LSEQ + (size_t)ch * CS) * DK;
    const float* kg = kin + ((size_t)head * LSEQ + (size_t)ch * CS) * DK;
    const float* vg = vin + ((size_t)head * LSEQ + (size_t)ch * CS) * DV;
    const float* st = g_state + (size_t)(head * NC + ch) * ST_STRIDE;

    const int tid = threadIdx.x, warp = tid >> 5, lane = tid & 31;
    const int wm = warp >> 1, wn = warp & 1, g = lane >> 2, tg = lane & 3;
    int rbase[2];
    rbase[0] = 16 * wm;
    rbase[1] = 240 - 16 * wm;

    for (int i = tid; i < CS * DK; i += 512) {
        int r = i >> 4, idx = i & 15;
        int t = r >> 4, rr = r & 15;
        sqp[((t * 8) + (rr & 7)) * 34 + idx * 2 + (rr >> 3)] = f2tf(qg[i] * 0.25f);
        sk4[r * 16 + (idx & 3) * 4 + (idx >> 2)] = f2tf(kg[i]);
    }
    if (tid < 256) {
        int t = tid >> 4, rr = tid & 15;
        sqp[((t * 8) + (rr & 7)) * 34 + 32 + (rr >> 3)] = 1.0f;  // idx 16 pad
        szs[tid] = 0.f;
    }
    for (int i = tid; i < CS * 16; i += 512) {
        int cc = i >> 4, f4 = (i & 15) * 4;
        float4 v = *(const float4*)&vg[cc * 64 + f4];
        int k8 = cc >> 3, jj = cc & 7, base = (jj & 3) * 2 + (jj >> 2);
        sBq[(k8 * NW + f4 + 0) * 8 + base] = f2tf(v.x);
        sBq[(k8 * NW + f4 + 1) * 8 + base] = f2tf(v.y);
        sBq[(k8 * NW + f4 + 2) * 8 + base] = f2tf(v.z);
        sBq[(k8 * NW + f4 + 3) * 8 + base] = f2tf(v.w);
    }
    lut_build(spd, spe, sw, spde, tid);
    __syncthreads();

    // Q fragments per mirrored tile (rows r0, r0+8 come paired)
    unsigned qf[2][2][4];
    #pragma unroll
    for (int mt = 0; mt < 2; mt++) {
        int qbase = (((rbase[mt] >> 4) * 8) + g) * 34;
        #pragma unroll
        for (int ks = 0; ks < 2; ks++) {
            float2 qa = *(float2*)&sqp[qbase + (8 * ks + tg) * 2];
            float2 qb = *(float2*)&sqp[qbase + (8 * ks + tg + 4) * 2];
            qf[mt][ks][0] = fas(qa.x);
            qf[mt][ks][1] = fas(qa.y);
            qf[mt][ks][2] = fas(qb.x);
            qf[mt][ks][3] = fas(qb.y);
        }
    }

    float c[2][4][4];
    #pragma unroll
    for (int mt = 0; mt < 2; mt++)
        #pragma unroll
        for (int nt = 0; nt < 4; nt++)
            #pragma unroll
            for (int u = 0; u < 4; u++) c[mt][nt][u] = 0.f;

    float zp[2][2];
    zp[0][0] = zp[0][1] = zp[1][0] = zp[1][1] = 0.f;
    const int srcA = (lane & ~3) + (tg >> 1), srcB = srcA + 2;
    const bool od = tg & 1;

    // ---- intra: barrier-free, per-tile column sweep ----
    #pragma unroll
    for (int mt = 0; mt < 2; mt++) {
        const int R = rbase[mt];
        const int nsteps = R / 8 + 2;       // cols [0, R+16)
        const int r0 = R + g;
        for (int js = 0; js < nsteps; js++) {
            float4 kb = *(float4*)&sk4[(8 * js + g) * 16 + tg * 4];
            unsigned b00 = fas(kb.x), b01 = fas(kb.y);
            unsigned b10 = fas(kb.z), b11 = fas(kb.w);
            float sf[4] = {0.f, 0.f, 0.f, 0.f};
            mma8(sf, qf[mt][0][0], qf[mt][0][1], qf[mt][0][2],
                 qf[mt][0][3], b00, b01);
            mma8(sf, qf[mt][1][0], qf[mt][1][1], qf[mt][1][2],
                 qf[mt][1][3], b10, b11);
            int jg = 8 * js + 2 * tg;
            float s0 = sf[0], s1 = sf[1], s2 = sf[2], s3 = sf[3];
            float v0 = (r0 >= jg)     ? fmaf(0.5f * s0, s0, s0 + 1.f) : 0.f;
            float v1 = (r0 >= jg + 1) ? fmaf(0.5f * s1, s1, s1 + 1.f) : 0.f;
            float v2 = (r0 + 8 >= jg)     ? fmaf(0.5f * s2, s2, s2 + 1.f) : 0.f;
            float v3 = (r0 + 8 >= jg + 1) ? fmaf(0.5f * s3, s3, s3 + 1.f) : 0.f;
            zp[mt][0] += v0 + v1;
            zp[mt][1] += v2 + v3;
            unsigned u0 = f2t(v0), u1 = f2t(v1);
            unsigned u2 = f2t(v2), u3 = f2t(v3);
            unsigned e0 = shflu(u0, srcA), o0 = shflu(u1, srcA);
            unsigned e1 = shflu(u2, srcA), o1 = shflu(u3, srcA);
            unsigned e2 = shflu(u0, srcB), o2 = shflu(u1, srcB);
            unsigned e3 = shflu(u2, srcB), o3 = shflu(u3, srcB);
            unsigned af0 = od ? o0 : e0;
            unsigned af1 = od ? o1 : e1;
            unsigned af2 = od ? o2 : e2;
            unsigned af3 = od ? o3 : e3;
            #pragma unroll
            for (int nt = 0; nt < 4; nt++) {
                int fc = 32 * wn + 8 * nt + g;
                uint2 bv = *(uint2*)&sBu[(js * NW + fc) * 8 + tg * 2];
                mma8(c[mt][nt], af0, af1, af2, af3, bv.x, bv.y);
            }
        }
    }

    // intra z merge: wn==0 warps own their rows exclusively
    if (wn == 0) {
        #pragma unroll
        for (int mt = 0; mt < 2; mt++)
            #pragma unroll
            for (int h = 0; h < 2; h++) {
                float v = zp[mt][h];
                v += __shfl_xor_sync(0xffffffffu, v, 1);
                v += __shfl_xor_sync(0xffffffffu, v, 2);
                if (tg == 0) szs[rbase[mt] + g + 8 * h] += v;
            }
    }
    __syncthreads();   // V reads + szs intra writes complete

    // restage sBq <- w * scanned state (paired rows); swst <- w * state[:,64]
    for (int i = tid; i < NP * 16; i += 512) {
        int pp = i >> 4, f4 = (i & 15) * 4;
        float w = sw[pp];
        float4 vv = *(const float4*)&st[pp * NW + f4];
        int k8 = pp >> 3, jj = pp & 7, base = (jj & 3) * 2 + (jj >> 2);
        sBq[(k8 * NW + f4 + 0) * 8 + base] = f2tf(w * vv.x);
        sBq[(k8 * NW + f4 + 1) * 8 + base] = f2tf(w * vv.y);
        sBq[(k8 * NW + f4 + 2) * 8 + base] = f2tf(w * vv.z);
        sBq[(k8 * NW + f4 + 3) * 8 + base] = f2tf(w * vv.w);
    }
    if (tid < NP) swst[tid] = sw[tid] * st[tid * NW + 64];
    __syncthreads();

    // inter z (scalar, split across thread pairs, packed indices)
    {
        int row = tid >> 1, half = tid & 1;
        int t = row >> 4, rr = row & 15;
        const float* qb = &sqp[((t * 8) + (rr & 7)) * 34 + (rr >> 3)];
        float zi = 0.f;
        int pa = half ? 77 : 0, pb = half ? 153 : 77;
        #pragma unroll 7
        for (int p = pa; p < pb; p++) {
            int de = spde[p];
            zi = fmaf(qb[de & 255] * qb[de >> 8], swst[p], zi);
        }
        zi += __shfl_xor_sync(0xffffffffu, zi, 1);
        if (!half) szs[row] += zi;
    }

    // ---- inter: C[256x64] += A[256x160] @ Bstate[160x64], unrolled ----
    const int colb = 32 * wn;
    #pragma unroll 5
    for (int ks = 0; ks < 20; ks++) {
        int p0 = 8 * ks + tg, p1 = p0 + 4;
        int d0 = spd[p0], e0 = spe[p0];
        int d1 = spd[p1], e1 = spe[p1];
        unsigned a[2][4];
        #pragma unroll
        for (int mt = 0; mt < 2; mt++) {
            int qbase = (((rbase[mt] >> 4) * 8) + g) * 34;
            float2 pd0 = *(float2*)&sqp[qbase + d0 * 2];
            float2 pe0 = *(float2*)&sqp[qbase + e0 * 2];
            float2 pd1 = *(float2*)&sqp[qbase + d1 * 2];
            float2 pe1 = *(float2*)&sqp[qbase + e1 * 2];
            a[mt][0] = fas(pd0.x * pe0.x);   // row r0,   p0
            a[mt][1] = fas(pd0.y * pe0.y);   // row r0+8, p0
            a[mt][2] = fas(pd1.x * pe1.x);   // row r0,   p1
            a[mt][3] = fas(pd1.y * pe1.y);   // row r0+8, p1
        }
        unsigned b[4][2];
        #pragma unroll
        for (int nt = 0; nt < 4; nt++) {
            uint2 bb = *(uint2*)&sBu[(ks * NW + colb + 8 * nt + g) * 8 + tg * 2];
            b[nt][0] = bb.x; b[nt][1] = bb.y;
        }
        #pragma unroll
        for (int mt = 0; mt < 2; mt++)
            #pragma unroll
            for (int nt = 0; nt < 4; nt++)
                mma8(c[mt][nt], a[mt][0], a[mt][1], a[mt][2],
                     a[mt][3], b[nt][0], b[nt][1]);
    }
    __syncthreads();

    // ---- epilogue: divide by z, store ----
    float* og = out + ((size_t)head * LSEQ + (size_t)ch * CS) * DV;
    #pragma unroll
    for (int mt = 0; mt < 2; mt++) {
        int r0 = rbase[mt] + g;
        float z0 = 1.f / (szs[r0] + 1e-6f);
        float z1 = 1.f / (szs[r0 + 8] + 1e-6f);
        #pragma unroll
        for (int nt = 0; nt < 4; nt++) {
            int f = 32 * wn + 8 * nt + 2 * tg;
            *(float2*)&og[r0 * 64 + f] =
                make_float2(c[mt][nt][0] * z0, c[mt][nt][1] * z0);
            *(float2*)&og[(r0 + 8) * 64 + f] =
                make_float2(c[mt][nt][2] * z1, c[mt][nt][3] * z1);
        }
    }
}

// ---------------------------------------------------------------------------
extern "C" void kernel_launch(void* const* d_in, const int* in_sizes, int n_in,
                              void* d_out, int out_size) {
    const float* q = (const float*)d_in[0];
    const float* k = (const float*)d_in[1];
    const float* v = (const float*)d_in[2];
    float* out = (float*)d_out;

    const int smem1 = (17 * SKQ_STRIDE + 32 * NW * 8 + 4 * NP) * (int)sizeof(float);
    const int smem3 = (128 * 34 + 256 * 16 + 32 * NW * 8 + 256 + 5 * NP) *
                      (int)sizeof(float);

    cudaFuncSetAttribute(k_build, cudaFuncAttributeMaxDynamicSharedMemorySize, smem1);
    cudaFuncSetAttribute(k_main,  cudaFuncAttributeMaxDynamicSharedMemorySize, smem3);

    k_build<<<dim3(BH, NC), 480, smem1>>>(k, v);
    k_scan<<<dim3(BH, 45), 256>>>();
    k_main<<<dim3(BH, NC), 512, smem3>>>(q, k, v, out);
}

// round 13
// speedup vs baseline: 1.5762x; 1.5762x over previous
#include <cuda_runtime.h>
#include <cstdint>

#define BH   32
#define LSEQ 4096
#define DK   16
#define DV   64
#define CS   256
#define NC   16

// Symmetric-pair state: 136 pair rows (d<=e) + 16 linear rows + 1 ones row,
// padded to 160 rows x 72 cols (64 v-cols + 1 aux-sum col + 7 zero pads).
#define NP   160
#define NW   72
#define ST_STRIDE (NP * NW)   // 11520

#define SKB_STRIDE 264        // k_build k layout stride (== 8 mod 32)
#define SV2_STRIDE 132        // packed-pair B tiles stride (== 4 mod 32)

__device__ float g_state[(size_t)BH * NC * ST_STRIDE];

__device__ __forceinline__ unsigned f2t(float x) {
    unsigned u;
    asm("cvt.rna.tf32.f32 %0, %1;" : "=r"(u) : "f"(x));
    return u;
}
__device__ __forceinline__ float f2tf(float x) { return __uint_as_float(f2t(x)); }

// pack two fp32 -> fp16x2 (lo in low half)
__device__ __forceinline__ unsigned pack2(float lo, float hi) {
    unsigned r;
    asm("cvt.rn.f16x2.f32 %0, %1, %2;" : "=r"(r) : "f"(hi), "f"(lo));
    return r;
}

__device__ __forceinline__ void mma16(float* c, unsigned a0, unsigned a1,
                                      unsigned a2, unsigned a3,
                                      unsigned b0, unsigned b1) {
    asm volatile(
        "mma.sync.aligned.m16n8k16.row.col.f32.f16.f16.f32 "
        "{%0,%1,%2,%3},{%4,%5,%6,%7},{%8,%9},{%0,%1,%2,%3};"
        : "+f"(c[0]), "+f"(c[1]), "+f"(c[2]), "+f"(c[3])
        : "r"(a0), "r"(a1), "r"(a2), "r"(a3), "r"(b0), "r"(b1));
}

// p -> (d, e, w). d,e in [0,16]; index 16 hits the pad slot (=1.0f).
// spde packs (2d | 2e<<8) for the z-scalar loop over the sqp layout.
__device__ __forceinline__ void lut_build(int* spd, int* spe, float* sw,
                                          int* spde, int tid) {
    if (tid < NP) {
        int p = tid, d = 0, e;
        float w;
        if (p < 136) {
            int base = 0;
            while (base + (16 - d) <= p) { base += 16 - d; d++; }
            e = d + (p - base);
            w = (d == e) ? 0.5f : 1.0f;
        } else if (p < 152) { d = p - 136; e = 16; w = 1.f; }
        else if (p == 152) { d = 16; e = 16; w = 1.f; }
        else               { d = 16; e = 16; w = 0.f; }
        spd[p] = d; spe[p] = e; sw[p] = w;
        spde[p] = (2 * d) | ((2 * e) << 8);
    }
}

// ---------------------------------------------------------------------------
// Kernel 1: state build = single GEMM  st[160x72] = A[160x256] @ B[256x72]
// fp16 m16n8k16; A built in registers from skb (fp32, c-adjacent pairs);
// B = V+aux staged as fp16x2 pairs over adjacent c. 480 threads, 2 CTAs/SM.
// ---------------------------------------------------------------------------
__global__ __launch_bounds__(480, 2)
void k_build(const float* __restrict__ kin, const float* __restrict__ vin) {
    const int head = blockIdx.x, ch = blockIdx.y;
    extern __shared__ float sm[];
    float* skb = sm;                         // [17][SKB_STRIDE] fp32 k (+ones)
    unsigned* sBu = (unsigned*)(skb + 17 * SKB_STRIDE);  // [72][SV2_STRIDE]
    int*   spd = (int*)(sBu + NW * SV2_STRIDE);
    int*   spe = spd + NP;
    float* sw  = (float*)(spe + NP);
    int*   spde = (int*)(sw + NP);

    const float* kg = kin + ((size_t)head * LSEQ + (size_t)ch * CS) * DK;
    const float* vg = vin + ((size_t)head * LSEQ + (size_t)ch * CS) * DV;
    float* st = g_state + (size_t)(head * NC + ch) * ST_STRIDE;

    const int tid = threadIdx.x, warp = tid >> 5, lane = tid & 31;
    const int wm = warp / 3, wn = warp % 3, g = lane >> 2, tg = lane & 3;
    const int rb = 32 * wm, cb = 24 * wn;

    // stage k: skb[idx][c] fp32, idx 16 = ones
    for (int i = tid; i < CS * DK; i += 480) {
        int cc = i >> 4, idx = i & 15;
        skb[idx * SKB_STRIDE + cc] = kg[i];
    }
    for (int i = tid; i < CS; i += 480) skb[16 * SKB_STRIDE + i] = 1.0f;
    // stage B: half2 pairs over (c=2cp, 2cp+1); cols 0..63 = V, 64 = ones
    for (int i = tid; i < 128 * 18; i += 480) {
        int cp = i / 18, fg = i - cp * 18, f4 = fg * 4;
        if (f4 < 64) {
            float4 x0 = *(const float4*)&vg[(2 * cp) * 64 + f4];
            float4 x1 = *(const float4*)&vg[(2 * cp + 1) * 64 + f4];
            sBu[(f4 + 0) * SV2_STRIDE + cp] = pack2(x0.x, x1.x);
            sBu[(f4 + 1) * SV2_STRIDE + cp] = pack2(x0.y, x1.y);
            sBu[(f4 + 2) * SV2_STRIDE + cp] = pack2(x0.z, x1.z);
            sBu[(f4 + 3) * SV2_STRIDE + cp] = pack2(x0.w, x1.w);
        } else {
            #pragma unroll
            for (int u = 0; u < 4; u++) {
                int f = f4 + u;
                sBu[f * SV2_STRIDE + cp] = (f == 64) ? 0x3C003C00u : 0u;
            }
        }
    }
    lut_build(spd, spe, sw, spde, tid);
    __syncthreads();

    int rd[2][2], re[2][2];
    #pragma unroll
    for (int mt = 0; mt < 2; mt++) {
        int r0 = rb + 16 * mt + g;
        rd[mt][0] = spd[r0];     re[mt][0] = spe[r0];
        rd[mt][1] = spd[r0 + 8]; re[mt][1] = spe[r0 + 8];
    }

    float c[2][3][4];
    #pragma unroll
    for (int mt = 0; mt < 2; mt++)
        #pragma unroll
        for (int nt = 0; nt < 3; nt++)
            #pragma unroll
            for (int u = 0; u < 4; u++) c[mt][nt][u] = 0.f;

    #pragma unroll 4
    for (int ks = 0; ks < 16; ks++) {
        const int c0 = 16 * ks + 2 * tg;
        unsigned a[2][4];
        #pragma unroll
        for (int mt = 0; mt < 2; mt++) {
            float2 pd0 = *(float2*)&skb[rd[mt][0] * SKB_STRIDE + c0];
            float2 pe0 = *(float2*)&skb[re[mt][0] * SKB_STRIDE + c0];
            float2 pd1 = *(float2*)&skb[rd[mt][1] * SKB_STRIDE + c0];
            float2 pe1 = *(float2*)&skb[re[mt][1] * SKB_STRIDE + c0];
            a[mt][0] = pack2(pd0.x * pe0.x, pd0.y * pe0.y);  // row r0, c0..c0+1
            a[mt][1] = pack2(pd1.x * pe1.x, pd1.y * pe1.y);  // row r0+8
            float2 qd0 = *(float2*)&skb[rd[mt][0] * SKB_STRIDE + c0 + 8];
            float2 qe0 = *(float2*)&skb[re[mt][0] * SKB_STRIDE + c0 + 8];
            float2 qd1 = *(float2*)&skb[rd[mt][1] * SKB_STRIDE + c0 + 8];
            float2 qe1 = *(float2*)&skb[re[mt][1] * SKB_STRIDE + c0 + 8];
            a[mt][2] = pack2(qd0.x * qe0.x, qd0.y * qe0.y);  // row r0, c0+8..9
            a[mt][3] = pack2(qd1.x * qe1.x, qd1.y * qe1.y);
        }
        #pragma unroll
        for (int nt = 0; nt < 3; nt++) {
            int fc = cb + 8 * nt + g;
            unsigned b0 = sBu[fc * SV2_STRIDE + 8 * ks + tg];
            unsigned b1 = sBu[fc * SV2_STRIDE + 8 * ks + tg + 4];
            #pragma unroll
            for (int mt = 0; mt < 2; mt++)
                mma16(c[mt][nt], a[mt][0], a[mt][1], a[mt][2], a[mt][3],
                      b0, b1);
        }
    }

    #pragma unroll
    for (int mt = 0; mt < 2; mt++)
        #pragma unroll
        for (int nt = 0; nt < 3; nt++) {
            int r0 = rb + 16 * mt + g, col = cb + 8 * nt + 2 * tg;
            *(float2*)&st[r0 * NW + col] =
                make_float2(c[mt][nt][0], c[mt][nt][1]);
            *(float2*)&st[(r0 + 8) * NW + col] =
                make_float2(c[mt][nt][2], c[mt][nt][3]);
        }
}

// ---------------------------------------------------------------------------
// Kernel 2: exclusive prefix scan over chunk axis. One element per thread.
// ---------------------------------------------------------------------------
__global__ void k_scan() {
    float* base = g_state + (size_t)blockIdx.x * NC * ST_STRIDE +
                  blockIdx.y * blockDim.x + threadIdx.x;
    float v[NC];
    #pragma unroll
    for (int c = 0; c < NC; c++) v[c] = base[(size_t)c * ST_STRIDE];
    float run = 0.f;
    #pragma unroll
    for (int c = 0; c < NC; c++) {
        float t = v[c];
        v[c] = run;
        run += t;
    }
    #pragma unroll
    for (int c = 0; c < NC; c++) base[(size_t)c * ST_STRIDE] = v[c];
}

// ---------------------------------------------------------------------------
// Kernel 3: output. 512 threads, 2 CTAs/SM. Mirrored row tiles.
// fp16 m16n8k16: S-mma C fragments pack DIRECTLY into AV A fragments
// (no shuffles). V / state staged as fp16x2 row-pairs.
// ---------------------------------------------------------------------------
__global__ __launch_bounds__(512, 2)
void k_main(const float* __restrict__ qin, const float* __restrict__ kin,
            const float* __restrict__ vin, float* __restrict__ out) {
    const int head = blockIdx.x, ch = blockIdx.y;
    extern __shared__ float sm[];
    float* sqp = sm;                           // [128][34] fp32 q (row pairs)
    unsigned* sk2 = (unsigned*)(sqp + 128 * 34);      // [256][8] fp16x2 k
    unsigned* sv2 = sk2 + 256 * 8;                    // [64][SV2_STRIDE]
    float* szs = (float*)(sv2 + 64 * SV2_STRIDE);     // [256]
    int*   spd = (int*)(szs + 256);
    int*   spe = spd + NP;
    float* sw  = (float*)(spe + NP);
    int*   spde = (int*)(sw + NP);
    float* swst = (float*)(spde + NP);         // [160] w*state[:,64]

    const float* qg = qin + ((size_t)head * LSEQ + (size_t)ch * CS) * DK;
    const float* kg = kin + ((size_t)head * LSEQ + (size_t)ch * CS) * DK;
    const float* vg = vin + ((size_t)head * LSEQ + (size_t)ch * CS) * DV;
    const float* st = g_state + (size_t)(head * NC + ch) * ST_STRIDE;

    const int tid = threadIdx.x, warp = tid >> 5, lane = tid & 31;
    const int wm = warp >> 1, wn = warp & 1, g = lane >> 2, tg = lane & 3;
    int rbase[2];
    rbase[0] = 16 * wm;
    rbase[1] = 240 - 16 * wm;

    // stage q (fp32 row-pair layout; idx 16 = ones pad)
    for (int i = tid; i < CS * DK; i += 512) {
        int r = i >> 4, idx = i & 15;
        int t = r >> 4, rr = r & 15;
        sqp[((t * 8) + (rr & 7)) * 34 + idx * 2 + (rr >> 3)] = f2tf(qg[i] * 0.25f);
    }
    if (tid < 256) {
        int t = tid >> 4, rr = tid & 15;
        sqp[((t * 8) + (rr & 7)) * 34 + 32 + (rr >> 3)] = 1.0f;
        szs[tid] = 0.f;
    }
    // stage k as fp16x2 idx-pairs: slot order (tg, tg+4) interleaved
    for (int i = tid; i < CS * 8; i += 512) {
        int r = i >> 3, t = i & 7;
        float2 kk = *(const float2*)&kg[r * 16 + 2 * t];
        sk2[r * 8 + (t & 3) * 2 + (t >> 2)] = pack2(kk.x, kk.y);
    }
    // stage V as fp16x2 pairs over adjacent chunk-rows
    for (int i = tid; i < 128 * 16; i += 512) {
        int jp = i >> 4, f4 = (i & 15) * 4;
        float4 x0 = *(const float4*)&vg[(2 * jp) * 64 + f4];
        float4 x1 = *(const float4*)&vg[(2 * jp + 1) * 64 + f4];
        sv2[(f4 + 0) * SV2_STRIDE + jp] = pack2(x0.x, x1.x);
        sv2[(f4 + 1) * SV2_STRIDE + jp] = pack2(x0.y, x1.y);
        sv2[(f4 + 2) * SV2_STRIDE + jp] = pack2(x0.z, x1.z);
        sv2[(f4 + 3) * SV2_STRIDE + jp] = pack2(x0.w, x1.w);
    }
    lut_build(spd, spe, sw, spde, tid);
    __syncthreads();

    // Q fragments per mirrored tile: a0..a3 of m16n8k16 (K = full DK=16)
    unsigned qf[2][4];
    #pragma unroll
    for (int mt = 0; mt < 2; mt++) {
        int qbase = (((rbase[mt] >> 4) * 8) + g) * 34;
        float2 t0 = *(float2*)&sqp[qbase + (2 * tg) * 2];
        float2 t1 = *(float2*)&sqp[qbase + (2 * tg + 1) * 2];
        float2 t2 = *(float2*)&sqp[qbase + (8 + 2 * tg) * 2];
        float2 t3 = *(float2*)&sqp[qbase + (9 + 2 * tg) * 2];
        qf[mt][0] = pack2(t0.x, t1.x);   // row r0+g,   idx 2tg..2tg+1
        qf[mt][1] = pack2(t0.y, t1.y);   // row r0+g+8
        qf[mt][2] = pack2(t2.x, t3.x);   // row r0+g,   idx 8+2tg..
        qf[mt][3] = pack2(t2.y, t3.y);
    }

    float c[2][4][4];
    #pragma unroll
    for (int mt = 0; mt < 2; mt++)
        #pragma unroll
        for (int nt = 0; nt < 4; nt++)
            #pragma unroll
            for (int u = 0; u < 4; u++) c[mt][nt][u] = 0.f;

    float zp[2][2];
    zp[0][0] = zp[0][1] = zp[1][0] = zp[1][1] = 0.f;

    // ---- intra: barrier-free; K=16 col-blocks; no shuffles ----
    #pragma unroll
    for (int mt = 0; mt < 2; mt++) {
        const int R = rbase[mt];
        const int nu = R / 16 + 1;          // 16-col blocks covering [0, R+16)
        const int r0 = R + g;
        for (int u = 0; u < nu; u++) {
            int j0 = 16 * u + g;
            uint2 kb0 = *(uint2*)&sk2[j0 * 8 + 2 * tg];          // block J0
            uint2 kb1 = *(uint2*)&sk2[(j0 + 8) * 8 + 2 * tg];    // block J1
            float sf0[4] = {0.f, 0.f, 0.f, 0.f};
            float sf1[4] = {0.f, 0.f, 0.f, 0.f};
            mma16(sf0, qf[mt][0], qf[mt][1], qf[mt][2], qf[mt][3],
                  kb0.x, kb0.y);
            mma16(sf1, qf[mt][0], qf[mt][1], qf[mt][2], qf[mt][3],
                  kb1.x, kb1.y);
            int jg0 = 16 * u + 2 * tg, jg1 = jg0 + 8;
            float v00 = (r0 >= jg0)     ? fmaf(0.5f * sf0[0], sf0[0], sf0[0] + 1.f) : 0.f;
            float v01 = (r0 >= jg0 + 1) ? fmaf(0.5f * sf0[1], sf0[1], sf0[1] + 1.f) : 0.f;
            float v02 = (r0 + 8 >= jg0)     ? fmaf(0.5f * sf0[2], sf0[2], sf0[2] + 1.f) : 0.f;
            float v03 = (r0 + 8 >= jg0 + 1) ? fmaf(0.5f * sf0[3], sf0[3], sf0[3] + 1.f) : 0.f;
            float v10 = (r0 >= jg1)     ? fmaf(0.5f * sf1[0], sf1[0], sf1[0] + 1.f) : 0.f;
            float v11 = (r0 >= jg1 + 1) ? fmaf(0.5f * sf1[1], sf1[1], sf1[1] + 1.f) : 0.f;
            float v12 = (r0 + 8 >= jg1)     ? fmaf(0.5f * sf1[2], sf1[2], sf1[2] + 1.f) : 0.f;
            float v13 = (r0 + 8 >= jg1 + 1) ? fmaf(0.5f * sf1[3], sf1[3], sf1[3] + 1.f) : 0.f;
            zp[mt][0] += v00 + v01 + v10 + v11;
            zp[mt][1] += v02 + v03 + v12 + v13;
            unsigned af0 = pack2(v00, v01);   // (g,  k 2tg..2tg+1)
            unsigned af1 = pack2(v02, v03);   // (g+8, k 2tg..)
            unsigned af2 = pack2(v10, v11);   // (g,  k 8+2tg..)
            unsigned af3 = pack2(v12, v13);
            #pragma unroll
            for (int nt = 0; nt < 4; nt++) {
                int fc = 32 * wn + 8 * nt + g;
                unsigned bv0 = sv2[fc * SV2_STRIDE + 8 * u + tg];
                unsigned bv1 = sv2[fc * SV2_STRIDE + 8 * u + tg + 4];
                mma16(c[mt][nt], af0, af1, af2, af3, bv0, bv1);
            }
        }
    }

    // intra z merge: wn==0 warps own their rows exclusively
    if (wn == 0) {
        #pragma unroll
        for (int mt = 0; mt < 2; mt++)
            #pragma unroll
            for (int h = 0; h < 2; h++) {
                float v = zp[mt][h];
                v += __shfl_xor_sync(0xffffffffu, v, 1);
                v += __shfl_xor_sync(0xffffffffu, v, 2);
                if (tg == 0) szs[rbase[mt] + g + 8 * h] += v;
            }
    }
    __syncthreads();   // V reads + szs intra writes complete

    // restage sv2 <- w*state as fp16x2 pairs over adjacent p; swst scalar col
    for (int i = tid; i < 80 * 16; i += 512) {
        int pp = i >> 4, f4 = (i & 15) * 4;
        float w0 = sw[2 * pp], w1 = sw[2 * pp + 1];
        float4 x0 = *(const float4*)&st[(2 * pp) * NW + f4];
        float4 x1 = *(const float4*)&st[(2 * pp + 1) * NW + f4];
        sv2[(f4 + 0) * SV2_STRIDE + pp] = pack2(w0 * x0.x, w1 * x1.x);
        sv2[(f4 + 1) * SV2_STRIDE + pp] = pack2(w0 * x0.y, w1 * x1.y);
        sv2[(f4 + 2) * SV2_STRIDE + pp] = pack2(w0 * x0.z, w1 * x1.z);
        sv2[(f4 + 3) * SV2_STRIDE + pp] = pack2(w0 * x0.w, w1 * x1.w);
    }
    if (tid < NP) swst[tid] = sw[tid] * st[tid * NW + 64];
    __syncthreads();

    // inter z (scalar, thread pairs, packed indices)
    {
        int row = tid >> 1, half = tid & 1;
        int t = row >> 4, rr = row & 15;
        const float* qb = &sqp[((t * 8) + (rr & 7)) * 34 + (rr >> 3)];
        float zi = 0.f;
        int pa = half ? 77 : 0, pb = half ? 153 : 77;
        #pragma unroll 7
        for (int p = pa; p < pb; p++) {
            int de = spde[p];
            zi = fmaf(qb[de & 255] * qb[de >> 8], swst[p], zi);
        }
        zi += __shfl_xor_sync(0xffffffffu, zi, 1);
        if (!half) szs[row] += zi;
    }

    // ---- inter: C[256x64] += A[256x160] @ Bstate[160x64]; 10 K=16 steps ----
    const int colb = 32 * wn;
    #pragma unroll 5
    for (int ks = 0; ks < 10; ks++) {
        int p0 = 16 * ks + 2 * tg;
        int d0 = spd[p0],     e0 = spe[p0];
        int d1 = spd[p0 + 1], e1 = spe[p0 + 1];
        int d2 = spd[p0 + 8], e2 = spe[p0 + 8];
        int d3 = spd[p0 + 9], e3 = spe[p0 + 9];
        unsigned a[2][4];
        #pragma unroll
        for (int mt = 0; mt < 2; mt++) {
            int qbase = (((rbase[mt] >> 4) * 8) + g) * 34;
            float2 pd0 = *(float2*)&sqp[qbase + d0 * 2];
            float2 pe0 = *(float2*)&sqp[qbase + e0 * 2];
            float2 pd1 = *(float2*)&sqp[qbase + d1 * 2];
            float2 pe1 = *(float2*)&sqp[qbase + e1 * 2];
            a[mt][0] = pack2(pd0.x * pe0.x, pd1.x * pe1.x);  // row r0,   p0..p0+1
            a[mt][1] = pack2(pd0.y * pe0.y, pd1.y * pe1.y);  // row r0+8
            float2 pd2 = *(float2*)&sqp[qbase + d2 * 2];
            float2 pe2 = *(float2*)&sqp[qbase + e2 * 2];
            float2 pd3 = *(float2*)&sqp[qbase + d3 * 2];
            float2 pe3 = *(float2*)&sqp[qbase + e3 * 2];
            a[mt][2] = pack2(pd2.x * pe2.x, pd3.x * pe3.x);  // row r0,   p0+8..9
            a[mt][3] = pack2(pd2.y * pe2.y, pd3.y * pe3.y);
        }
        #pragma unroll
        for (int nt = 0; nt < 4; nt++) {
            int fc = colb + 8 * nt + g;
            unsigned b0 = sv2[fc * SV2_STRIDE + 8 * ks + tg];
            unsigned b1 = sv2[fc * SV2_STRIDE + 8 * ks + tg + 4];
            #pragma unroll
            for (int mt = 0; mt < 2; mt++)
                mma16(c[mt][nt], a[mt][0], a[mt][1], a[mt][2], a[mt][3],
                      b0, b1);
        }
    }
    __syncthreads();

    // ---- epilogue: divide by z, store ----
    float* og = out + ((size_t)head * LSEQ + (size_t)ch * CS) * DV;
    #pragma unroll
    for (int mt = 0; mt < 2; mt++) {
        int r0 = rbase[mt] + g;
        float z0 = 1.f / (szs[r0] + 1e-6f);
        float z1 = 1.f / (szs[r0 + 8] + 1e-6f);
        #pragma unroll
        for (int nt = 0; nt < 4; nt++) {
            int f = 32 * wn + 8 * nt + 2 * tg;
            *(float2*)&og[r0 * 64 + f] =
                make_float2(c[mt][nt][0] * z0, c[mt][nt][1] * z0);
            *(float2*)&og[(r0 + 8) * 64 + f] =
                make_float2(c[mt][nt][2] * z1, c[mt][nt][3] * z1);
        }
    }
}

// ---------------------------------------------------------------------------
extern "C" void kernel_launch(void* const* d_in, const int* in_sizes, int n_in,
                              void* d_out, int out_size) {
    const float* q = (const float*)d_in[0];
    const float* k = (const float*)d_in[1];
    const float* v = (const float*)d_in[2];
    float* out = (float*)d_out;

    const int smem1 = (17 * SKB_STRIDE + NW * SV2_STRIDE + 4 * NP) *
                      (int)sizeof(float);
    const int smem3 = (128 * 34 + 256 * 8 + 64 * SV2_STRIDE + 256 + 5 * NP) *
                      (int)sizeof(float);

    cudaFuncSetAttribute(k_build, cudaFuncAttributeMaxDynamicSharedMemorySize, smem1);
    cudaFuncSetAttribute(k_main,  cudaFuncAttributeMaxDynamicSharedMemorySize, smem3);

    k_build<<<dim3(BH, NC), 480, smem1>>>(k, v);
    k_scan<<<dim3(BH, 45), 256>>>();
    k_main<<<dim3(BH, NC), 512, smem3>>>(q, k, v, out);
}